// round 15
// baseline (speedup 1.0000x reference)
#include <cuda_runtime.h>
#include <cuda_bf16.h>
#include <math.h>

#define N_POS 256
#define D_DIM 128
#define N_HEADS 4
#define C_DIM 32
#define ROWS (N_POS * N_POS)   // 65536

#define LOG2E 1.4426950408889634f

// ---------------- scratch (static device arrays) ----------------
__device__ __nv_bfloat16 g_qb[N_POS * N_HEADS * N_POS * C_DIM];   // [i][h][j][c]
__device__ __nv_bfloat16 g_kb[N_POS * N_HEADS * N_POS * C_DIM];   // [i][h][j][c]
__device__ __nv_bfloat16 g_vT[N_POS * N_HEADS * C_DIM * N_POS];   // [i][h][c][j]
__device__ __nv_bfloat16 g_gb[N_POS * N_HEADS * N_POS * C_DIM];   // sigmoid gate [i][h][j][c]
__device__ __nv_bfloat16 g_ogb[ROWS * D_DIM];                     // gated attn out (bf16)
__device__ __nv_bfloat16 g_trib[N_HEADS * ROWS];                  // [h][q*256+k] bf16 (x log2e)
__device__ __nv_bfloat16 g_wT[4][D_DIM * D_DIM];                  // q,k,v,g as [n][k] bf16
__device__ __nv_bfloat16 g_woT[D_DIM * D_DIM];                    // [d][hc] bf16

// ---------------- helpers ----------------
__device__ __forceinline__ void mma_bf16(float* c, const unsigned* a, const unsigned* b) {
    asm volatile(
        "mma.sync.aligned.m16n8k16.row.col.f32.bf16.bf16.f32 "
        "{%0,%1,%2,%3}, {%4,%5,%6,%7}, {%8,%9}, {%0,%1,%2,%3};\n"
        : "+f"(c[0]), "+f"(c[1]), "+f"(c[2]), "+f"(c[3])
        : "r"(a[0]), "r"(a[1]), "r"(a[2]), "r"(a[3]), "r"(b[0]), "r"(b[1]));
}

__device__ __forceinline__ void ldsm_x4(unsigned* d, const __nv_bfloat16* p) {
    unsigned addr = (unsigned)__cvta_generic_to_shared(p);
    asm volatile("ldmatrix.sync.aligned.m8n8.x4.shared.b16 {%0,%1,%2,%3}, [%4];"
        : "=r"(d[0]), "=r"(d[1]), "=r"(d[2]), "=r"(d[3]) : "r"(addr));
}

__device__ __forceinline__ unsigned pack_bf16(float lo, float hi) {
    __nv_bfloat162 t = __float22bfloat162_rn(make_float2(lo, hi));
    return *(unsigned*)&t;
}

__device__ __forceinline__ float ex2(float x) {
    float y;
    asm("ex2.approx.ftz.f32 %0, %1;" : "=f"(y) : "f"(x));
    return y;
}

__device__ __forceinline__ float frcp(float x) {
    float y;
    asm("rcp.approx.ftz.f32 %0, %1;" : "=f"(y) : "f"(x));
    return y;
}

// ---------------- kernel 0: weight transpose to bf16 ----------------
__global__ __launch_bounds__(256) void k_setup(
    const float* __restrict__ wq, const float* __restrict__ wk,
    const float* __restrict__ wv, const float* __restrict__ wg,
    const float* __restrict__ wo)
{
    for (int idx = blockIdx.x * 256 + threadIdx.x; idx < 5 * 16384; idx += gridDim.x * 256) {
        const int m = idx >> 14, r = idx & 16383;
        const int k = r >> 7, n = r & 127;
        const float* src = (m == 0) ? wq : (m == 1) ? wk : (m == 2) ? wv : (m == 3) ? wg : wo;
        float v = __ldg(src + r);
        if (m == 0) v *= 0.17677669529663687f * LOG2E;   // c^-0.5 and log2e folded into wq
        __nv_bfloat16 bv = __float2bfloat16(v);
        if (m < 4) g_wT[m][n * 128 + k] = bv;
        else       g_woT[n * 128 + k] = bv;
    }
}

// ---------------- kernel 1: LN + 4 projections + triangle bias ----------------
#define SA 136   // bf16 row stride (GEMM smem)
#define VST 72   // V staging stride (bf16)
__global__ __launch_bounds__(256) void k_proj(
    const float* __restrict__ Z_raw,
    const float* __restrict__ ln_w, const float* __restrict__ ln_b,
    const float* __restrict__ w_b, const float* __restrict__ bg)
{
    extern __shared__ __nv_bfloat16 smb[];
    __nv_bfloat16* zn = smb;                 // [64][SA]
    __nv_bfloat16* ws = smb + 64 * SA;       // [128][SA]  (also V-transpose staging)
    const int tid  = threadIdx.x;
    const int row0 = blockIdx.x * 64;
    const int warp = tid >> 5, lane = tid & 31;

    // --- LayerNorm -> bf16 smem ---
    for (int r = warp; r < 64; r += 8) {
        const float4 x = ((const float4*)(Z_raw + (size_t)(row0 + r) * D_DIM))[lane];
        float s  = x.x + x.y + x.z + x.w;
        float ss = x.x * x.x + x.y * x.y + x.z * x.z + x.w * x.w;
        #pragma unroll
        for (int o = 16; o > 0; o >>= 1) {
            s  += __shfl_xor_sync(0xffffffffu, s, o);
            ss += __shfl_xor_sync(0xffffffffu, ss, o);
        }
        const float mu  = s * (1.0f / 128.0f);
        const float inv = rsqrtf(ss * (1.0f / 128.0f) - mu * mu + 1e-5f);
        const int c = lane * 4;
        float v0 = (x.x - mu) * inv * __ldg(ln_w + c + 0) + __ldg(ln_b + c + 0);
        float v1 = (x.y - mu) * inv * __ldg(ln_w + c + 1) + __ldg(ln_b + c + 1);
        float v2 = (x.z - mu) * inv * __ldg(ln_w + c + 2) + __ldg(ln_b + c + 2);
        float v3 = (x.w - mu) * inv * __ldg(ln_w + c + 3) + __ldg(ln_b + c + 3);
        __nv_bfloat162* zr = (__nv_bfloat162*)(zn + r * SA + c);
        zr[0] = __float22bfloat162_rn(make_float2(v0, v1));
        zr[1] = __float22bfloat162_rn(make_float2(v2, v3));
    }
    __syncthreads();

    // --- triangle bias (bf16 out, pre-scaled by log2e) ---
    {
        const int r = tid >> 2, h = tid & 3;
        float acc = 0.0f;
        #pragma unroll 8
        for (int kk = 0; kk < D_DIM; kk++)
            acc = fmaf(__bfloat162float(zn[r * SA + kk]), __ldg(w_b + kk * N_HEADS + h), acc);
        g_trib[h * ROWS + row0 + r] = __float2bfloat16(acc * LOG2E);
    }

    // --- A fragments (reused across all 4 weight matrices) ---
    const int warp_m = warp & 3, warp_n = warp >> 2;
    const int r0 = warp_m * 16 + (lane >> 2);   // local row 0..63
    const int r1 = r0 + 8;
    unsigned afr[8][4];
    #pragma unroll
    for (int kt = 0; kt < 8; kt++) {
        const __nv_bfloat16* a0 = zn + r0 * SA + kt * 16 + (lane & 3) * 2;
        const __nv_bfloat16* a1 = zn + r1 * SA + kt * 16 + (lane & 3) * 2;
        afr[kt][0] = *(const unsigned*)a0;
        afr[kt][1] = *(const unsigned*)a1;
        afr[kt][2] = *(const unsigned*)(a0 + 8);
        afr[kt][3] = *(const unsigned*)(a1 + 8);
    }

    const int iblk = row0 >> 8, jbase = row0 & 255;

    for (int m = 0; m < 4; m++) {
        __syncthreads();
        const __nv_bfloat16* Wsrc = g_wT[m];
        for (int idx = tid; idx < 2048; idx += 256) {
            const int n = idx >> 4, seg = idx & 15;
            *(uint4*)(ws + n * SA + seg * 8) = *(const uint4*)(Wsrc + n * 128 + seg * 8);
        }
        __syncthreads();

        float acc[8][4];
        #pragma unroll
        for (int nt = 0; nt < 8; nt++)
            #pragma unroll
            for (int j = 0; j < 4; j++) acc[nt][j] = 0.0f;

        #pragma unroll
        for (int kt = 0; kt < 8; kt++) {
            #pragma unroll
            for (int nt = 0; nt < 8; nt++) {
                const __nv_bfloat16* bp =
                    ws + (warp_n * 64 + nt * 8 + (lane >> 2)) * SA + kt * 16 + (lane & 3) * 2;
                unsigned b[2] = { *(const unsigned*)bp, *(const unsigned*)(bp + 8) };
                mma_bf16(acc[nt], afr[kt], b);
            }
        }

        if (m == 2) {
            // stage V transposed through smem (reuse ws)
            __syncthreads();
            #pragma unroll
            for (int nt = 0; nt < 8; nt++) {
                const int col = warp_n * 64 + nt * 8 + (lane & 3) * 2;
                ws[col * VST + r0]       = __float2bfloat16(acc[nt][0]);
                ws[(col + 1) * VST + r0] = __float2bfloat16(acc[nt][1]);
                ws[col * VST + r1]       = __float2bfloat16(acc[nt][2]);
                ws[(col + 1) * VST + r1] = __float2bfloat16(acc[nt][3]);
            }
            __syncthreads();
            for (int idx = tid; idx < 1024; idx += 256) {
                const int col = idx >> 3, seg = idx & 7;
                *(uint4*)(g_vT + (((size_t)iblk * 4 + (col >> 5)) * 32 + (col & 31)) * 256
                          + jbase + seg * 8) =
                    *(const uint4*)(ws + col * VST + seg * 8);
            }
        } else {
            const int gr0 = row0 + r0, gr1 = row0 + r1;
            #pragma unroll
            for (int nt = 0; nt < 8; nt++) {
                const int col = warp_n * 64 + nt * 8 + (lane & 3) * 2;
                const int h = col >> 5, c = col & 31;
                const int j0 = gr0 & 255, j1 = gr1 & 255;
                if (m < 2) {
                    __nv_bfloat16* dst = (m == 0) ? g_qb : g_kb;
                    *(__nv_bfloat162*)(dst + ((iblk * 4 + h) * 256 + j0) * 32 + c) =
                        __float22bfloat162_rn(make_float2(acc[nt][0], acc[nt][1]));
                    *(__nv_bfloat162*)(dst + ((iblk * 4 + h) * 256 + j1) * 32 + c) =
                        __float22bfloat162_rn(make_float2(acc[nt][2], acc[nt][3]));
                } else {
                    const float2 bgv = __ldg((const float2*)(bg + col));
                    const float g00 = 1.0f / (1.0f + __expf(-(acc[nt][0] + bgv.x)));
                    const float g01 = 1.0f / (1.0f + __expf(-(acc[nt][1] + bgv.y)));
                    const float g10 = 1.0f / (1.0f + __expf(-(acc[nt][2] + bgv.x)));
                    const float g11 = 1.0f / (1.0f + __expf(-(acc[nt][3] + bgv.y)));
                    *(__nv_bfloat162*)(g_gb + ((iblk * 4 + h) * 256 + j0) * 32 + c) =
                        __float22bfloat162_rn(make_float2(g00, g01));
                    *(__nv_bfloat162*)(g_gb + ((iblk * 4 + h) * 256 + j1) * 32 + c) =
                        __float22bfloat162_rn(make_float2(g10, g11));
                }
            }
        }
    }
}

// ---------------- kernel 2: attention per (i,h) ----------------
// 64-key tiles (sacc[8][4] = 32 regs) -> reg cap 102 -> 5 blocks/SM.
#define SK 40     // Ks bf16 row stride
#define SV 264    // VsT bf16 row stride
__global__ __launch_bounds__(128, 5) void k_attn(const float* __restrict__ Z_mask)
{
    extern __shared__ __nv_bfloat16 smb[];
    __nv_bfloat16* Ks  = smb;                    // [256][SK]
    __nv_bfloat16* VsT = Ks + 256 * SK;          // [32][SV]
    float* ms = (float*)(VsT + 32 * SV);         // [256]
    const int i = blockIdx.x, h = blockIdx.y;
    const int tid = threadIdx.x;
    const int warp = tid >> 5, lane = tid & 31;

    const size_t base = (size_t)(i * N_HEADS + h) * N_POS * C_DIM;
    for (int idx = tid; idx < 1024; idx += 128) {
        const int j = idx >> 2, seg = idx & 3;
        *(uint4*)(Ks + j * SK + seg * 8) = *(const uint4*)(g_kb + base + j * 32 + seg * 8);
    }
    for (int idx = tid; idx < 1024; idx += 128) {
        const int c = idx >> 5, seg = idx & 31;
        *(uint4*)(VsT + c * SV + seg * 8) = *(const uint4*)(g_vT + base + c * 256 + seg * 8);
    }
    for (int kk = tid; kk < 256; kk += 128)
        ms[kk] = (1e9f * LOG2E) * (__ldg(Z_mask + i * N_POS + kk) - 1.0f);
    __syncthreads();

    const __nv_bfloat16* tribh = g_trib + (size_t)h * ROWS;
    const int qt = (lane & 3) * 2;

    for (int chunk = 0; chunk < 4; chunk++) {
        const int r0 = chunk * 64 + warp * 16 + (lane >> 2);
        const int r1 = r0 + 8;

        unsigned qa[2][4];
        {
            const __nv_bfloat16* q0 = g_qb + base + (size_t)r0 * 32 + qt;
            const __nv_bfloat16* q1 = g_qb + base + (size_t)r1 * 32 + qt;
            #pragma unroll
            for (int kt = 0; kt < 2; kt++) {
                qa[kt][0] = *(const unsigned*)(q0 + kt * 16);
                qa[kt][1] = *(const unsigned*)(q1 + kt * 16);
                qa[kt][2] = *(const unsigned*)(q0 + kt * 16 + 8);
                qa[kt][3] = *(const unsigned*)(q1 + kt * 16 + 8);
            }
        }

        float oacc[4][4];
        #pragma unroll
        for (int vt = 0; vt < 4; vt++)
            #pragma unroll
            for (int j = 0; j < 4; j++) oacc[vt][j] = 0.0f;
        float s0 = 0.0f, s1 = 0.0f;

        const __nv_bfloat16* t0p = tribh + (size_t)r0 * 256;
        const __nv_bfloat16* t1p = tribh + (size_t)r1 * 256;

        #pragma unroll
        for (int kb = 0; kb < 4; kb++) {
            float sacc[8][4];
            // init with trib + mask
            #pragma unroll
            for (int nt = 0; nt < 8; nt++) {
                const int col = kb * 64 + nt * 8 + qt;
                const float2 tb0 = __bfloat1622float2(*(const __nv_bfloat162*)(t0p + col));
                const float2 tb1 = __bfloat1622float2(*(const __nv_bfloat162*)(t1p + col));
                const float2 mv  = *(const float2*)(ms + col);
                sacc[nt][0] = tb0.x + mv.x; sacc[nt][1] = tb0.y + mv.y;
                sacc[nt][2] = tb1.x + mv.x; sacc[nt][3] = tb1.y + mv.y;
            }
            // S = Q K^T
            #pragma unroll
            for (int nt = 0; nt < 8; nt++) {
                const __nv_bfloat16* kp =
                    Ks + (kb * 64 + nt * 8 + (lane >> 2)) * SK + qt;
                unsigned b0[2] = { *(const unsigned*)kp,        *(const unsigned*)(kp + 8) };
                mma_bf16(sacc[nt], qa[0], b0);
                unsigned b1[2] = { *(const unsigned*)(kp + 16), *(const unsigned*)(kp + 24) };
                mma_bf16(sacc[nt], qa[1], b1);
            }
            // P = exp2(S)
            #pragma unroll
            for (int nt = 0; nt < 8; nt++) {
                sacc[nt][0] = ex2(sacc[nt][0]); s0 += sacc[nt][0];
                sacc[nt][1] = ex2(sacc[nt][1]); s0 += sacc[nt][1];
                sacc[nt][2] = ex2(sacc[nt][2]); s1 += sacc[nt][2];
                sacc[nt][3] = ex2(sacc[nt][3]); s1 += sacc[nt][3];
            }
            // O += P V
            #pragma unroll
            for (int kt = 0; kt < 4; kt++) {
                unsigned pa[4];
                pa[0] = pack_bf16(sacc[2 * kt][0],     sacc[2 * kt][1]);
                pa[1] = pack_bf16(sacc[2 * kt][2],     sacc[2 * kt][3]);
                pa[2] = pack_bf16(sacc[2 * kt + 1][0], sacc[2 * kt + 1][1]);
                pa[3] = pack_bf16(sacc[2 * kt + 1][2], sacc[2 * kt + 1][3]);
                #pragma unroll
                for (int vt = 0; vt < 4; vt++) {
                    const __nv_bfloat16* vp =
                        VsT + (vt * 8 + (lane >> 2)) * SV + kb * 64 + kt * 16 + qt;
                    unsigned b[2] = { *(const unsigned*)vp, *(const unsigned*)(vp + 8) };
                    mma_bf16(oacc[vt], pa, b);
                }
            }
        }

        s0 += __shfl_xor_sync(0xffffffffu, s0, 1);
        s0 += __shfl_xor_sync(0xffffffffu, s0, 2);
        s1 += __shfl_xor_sync(0xffffffffu, s1, 1);
        s1 += __shfl_xor_sync(0xffffffffu, s1, 2);
        const float inv0 = frcp(s0), inv1 = frcp(s1);

        const size_t grow0 = (size_t)i * 256 + r0;
        const size_t grow1 = (size_t)i * 256 + r1;
        #pragma unroll
        for (int vt = 0; vt < 4; vt++) {
            const int colc = vt * 8 + qt;
            const float2 gv0 = __bfloat1622float2(
                *(const __nv_bfloat162*)(g_gb + base + (size_t)r0 * 32 + colc));
            const float2 gv1 = __bfloat1622float2(
                *(const __nv_bfloat162*)(g_gb + base + (size_t)r1 * 32 + colc));
            *(__nv_bfloat162*)(g_ogb + grow0 * D_DIM + h * 32 + colc) =
                __float22bfloat162_rn(make_float2(oacc[vt][0] * inv0 * gv0.x,
                                                  oacc[vt][1] * inv0 * gv0.y));
            *(__nv_bfloat162*)(g_ogb + grow1 * D_DIM + h * 32 + colc) =
                __float22bfloat162_rn(make_float2(oacc[vt][2] * inv1 * gv1.x,
                                                  oacc[vt][3] * inv1 * gv1.y));
        }
    }
}

// ---------------- kernel 3: output projection + bias + residual ----------------
// R6 structure + ldmatrix B-fragments (measured win in R12: 29.6us).
__global__ __launch_bounds__(256) void k_out(
    const float* __restrict__ Z_raw,
    const float* __restrict__ out_bias, float* __restrict__ out)
{
    extern __shared__ __nv_bfloat16 smb[];
    __nv_bfloat16* os = smb;                 // [64][SA]
    __nv_bfloat16* ws = smb + 64 * SA;       // [128][SA]
    const int tid  = threadIdx.x;
    const int warp = tid >> 5, lane = tid & 31;
    const int warp_m = warp & 3, warp_n = warp >> 2;
    const int lr0 = warp_m * 16 + (lane >> 2);
    const int lr1 = lr0 + 8;

    for (int idx = tid; idx < 2048; idx += 256) {
        const int n = idx >> 4, seg = idx & 15;
        *(uint4*)(ws + n * SA + seg * 8) = *(const uint4*)(g_woT + n * 128 + seg * 8);
    }

    for (int t = 0; t < 2; t++) {
        const int row0 = blockIdx.x * 128 + t * 64;
        __syncthreads();
        for (int idx = tid; idx < 1024; idx += 256) {
            const int r = idx >> 4, seg = idx & 15;
            *(uint4*)(os + r * SA + seg * 8) =
                *(const uint4*)(g_ogb + (size_t)(row0 + r) * D_DIM + seg * 8);
        }
        __syncthreads();

        unsigned afr[8][4];
        #pragma unroll
        for (int kt = 0; kt < 8; kt++) {
            const __nv_bfloat16* a0 = os + lr0 * SA + kt * 16 + (lane & 3) * 2;
            const __nv_bfloat16* a1 = os + lr1 * SA + kt * 16 + (lane & 3) * 2;
            afr[kt][0] = *(const unsigned*)a0;
            afr[kt][1] = *(const unsigned*)a1;
            afr[kt][2] = *(const unsigned*)(a0 + 8);
            afr[kt][3] = *(const unsigned*)(a1 + 8);
        }

        float acc[8][4];
        #pragma unroll
        for (int nt = 0; nt < 8; nt++)
            #pragma unroll
            for (int j = 0; j < 4; j++) acc[nt][j] = 0.0f;

        #pragma unroll
        for (int kt = 0; kt < 8; kt++) {
            #pragma unroll
            for (int np = 0; np < 4; np++) {
                unsigned bm[4];
                const __nv_bfloat16* bp =
                    ws + (warp_n * 64 + np * 16 + (lane >> 4) * 8 + (lane & 7)) * SA
                       + kt * 16 + ((lane >> 3) & 1) * 8;
                ldsm_x4(bm, bp);
                mma_bf16(acc[np * 2],     afr[kt], bm);
                mma_bf16(acc[np * 2 + 1], afr[kt], bm + 2);
            }
        }

        const size_t gr0 = row0 + lr0, gr1 = row0 + lr1;
        #pragma unroll
        for (int nt = 0; nt < 8; nt++) {
            const int col = warp_n * 64 + nt * 8 + (lane & 3) * 2;
            const float2 ob = *(const float2*)(out_bias + col);
            const float2 z0 = *(const float2*)(Z_raw + gr0 * D_DIM + col);
            const float2 z1 = *(const float2*)(Z_raw + gr1 * D_DIM + col);
            *(float2*)(out + gr0 * D_DIM + col) =
                make_float2(acc[nt][0] + ob.x + z0.x, acc[nt][1] + ob.y + z0.y);
            *(float2*)(out + gr1 * D_DIM + col) =
                make_float2(acc[nt][2] + ob.x + z1.x, acc[nt][3] + ob.y + z1.y);
        }
    }
}

// ---------------------------------------------------------------------------
extern "C" void kernel_launch(void* const* d_in, const int* in_sizes, int n_in,
                              void* d_out, int out_size)
{
    (void)in_sizes; (void)n_in; (void)out_size;
    const float* Z_raw    = (const float*)d_in[0];
    const float* Z_mask   = (const float*)d_in[1];
    const float* ln_w     = (const float*)d_in[2];
    const float* ln_b     = (const float*)d_in[3];
    const float* w_b      = (const float*)d_in[4];
    const float* wq       = (const float*)d_in[5];
    const float* wk       = (const float*)d_in[6];
    const float* wv       = (const float*)d_in[7];
    const float* wg       = (const float*)d_in[8];
    const float* bg       = (const float*)d_in[9];
    const float* wo       = (const float*)d_in[10];
    const float* out_bias = (const float*)d_in[11];
    float* out = (float*)d_out;

    const int smem_gemm = (64 * SA + 128 * SA) * 2;                    // 52224
    const int smem_attn = (256 * SK + 32 * SV) * 2 + 256 * 4;          // 38400

    cudaFuncSetAttribute(k_proj, cudaFuncAttributeMaxDynamicSharedMemorySize, smem_gemm);
    cudaFuncSetAttribute(k_attn, cudaFuncAttributeMaxDynamicSharedMemorySize, smem_attn);
    cudaFuncSetAttribute(k_out,  cudaFuncAttributeMaxDynamicSharedMemorySize, smem_gemm);

    k_setup<<<160, 256>>>(wq, wk, wv, wg, wo);
    k_proj<<<ROWS / 64, 256, smem_gemm>>>(Z_raw, ln_w, ln_b, w_b, bg);
    k_attn<<<dim3(N_POS, N_HEADS), 128, smem_attn>>>(Z_mask);
    k_out<<<ROWS / 128, 256, smem_gemm>>>(Z_raw, out_bias, out);
}

// round 16
// speedup vs baseline: 1.0832x; 1.0832x over previous
#include <cuda_runtime.h>
#include <cuda_bf16.h>
#include <math.h>

#define N_POS 256
#define D_DIM 128
#define N_HEADS 4
#define C_DIM 32
#define ROWS (N_POS * N_POS)   // 65536

#define LOG2E 1.4426950408889634f

// ---------------- scratch (static device arrays) ----------------
__device__ __nv_bfloat16 g_qb[N_POS * N_HEADS * N_POS * C_DIM];   // [i][h][j][c]
__device__ __nv_bfloat16 g_kb[N_POS * N_HEADS * N_POS * C_DIM];   // [i][h][j][c]
__device__ __nv_bfloat16 g_vT[N_POS * N_HEADS * C_DIM * N_POS];   // [i][h][c][j]
__device__ __nv_bfloat16 g_gb[N_POS * N_HEADS * N_POS * C_DIM];   // sigmoid gate [i][h][j][c]
__device__ __nv_bfloat16 g_ogb[ROWS * D_DIM];                     // gated attn out (bf16)
__device__ __nv_bfloat16 g_trib[N_HEADS * ROWS];                  // [h][q*256+k] bf16 (x log2e)
__device__ __nv_bfloat16 g_wT[4][D_DIM * D_DIM];                  // q,k,v,g as [n][k] bf16
__device__ __nv_bfloat16 g_woT[D_DIM * D_DIM];                    // [d][hc] bf16

// ---------------- helpers ----------------
__device__ __forceinline__ void mma_bf16(float* c, const unsigned* a, const unsigned* b) {
    asm volatile(
        "mma.sync.aligned.m16n8k16.row.col.f32.bf16.bf16.f32 "
        "{%0,%1,%2,%3}, {%4,%5,%6,%7}, {%8,%9}, {%0,%1,%2,%3};\n"
        : "+f"(c[0]), "+f"(c[1]), "+f"(c[2]), "+f"(c[3])
        : "r"(a[0]), "r"(a[1]), "r"(a[2]), "r"(a[3]), "r"(b[0]), "r"(b[1]));
}

__device__ __forceinline__ void ldsm_x4(unsigned* d, const __nv_bfloat16* p) {
    unsigned addr = (unsigned)__cvta_generic_to_shared(p);
    asm volatile("ldmatrix.sync.aligned.m8n8.x4.shared.b16 {%0,%1,%2,%3}, [%4];"
        : "=r"(d[0]), "=r"(d[1]), "=r"(d[2]), "=r"(d[3]) : "r"(addr));
}

__device__ __forceinline__ unsigned pack_bf16(float lo, float hi) {
    __nv_bfloat162 t = __float22bfloat162_rn(make_float2(lo, hi));
    return *(unsigned*)&t;
}

__device__ __forceinline__ float ex2(float x) {
    float y;
    asm("ex2.approx.ftz.f32 %0, %1;" : "=f"(y) : "f"(x));
    return y;
}

__device__ __forceinline__ float frcp(float x) {
    float y;
    asm("rcp.approx.ftz.f32 %0, %1;" : "=f"(y) : "f"(x));
    return y;
}

// ---------------- kernel 0: weight transpose to bf16 ----------------
__global__ __launch_bounds__(256) void k_setup(
    const float* __restrict__ wq, const float* __restrict__ wk,
    const float* __restrict__ wv, const float* __restrict__ wg,
    const float* __restrict__ wo)
{
    for (int idx = blockIdx.x * 256 + threadIdx.x; idx < 5 * 16384; idx += gridDim.x * 256) {
        const int m = idx >> 14, r = idx & 16383;
        const int k = r >> 7, n = r & 127;
        const float* src = (m == 0) ? wq : (m == 1) ? wk : (m == 2) ? wv : (m == 3) ? wg : wo;
        float v = __ldg(src + r);
        if (m == 0) v *= 0.17677669529663687f * LOG2E;   // c^-0.5 and log2e folded into wq
        __nv_bfloat16 bv = __float2bfloat16(v);
        if (m < 4) g_wT[m][n * 128 + k] = bv;
        else       g_woT[n * 128 + k] = bv;
    }
}

// ---------------- kernel 1: LN + 4 projections + triangle bias ----------------
#define SA 136   // bf16 row stride (GEMM smem)
#define VST 72   // V staging stride (bf16)
__global__ __launch_bounds__(256) void k_proj(
    const float* __restrict__ Z_raw,
    const float* __restrict__ ln_w, const float* __restrict__ ln_b,
    const float* __restrict__ w_b, const float* __restrict__ bg)
{
    extern __shared__ __nv_bfloat16 smb[];
    __nv_bfloat16* zn = smb;                 // [64][SA]
    __nv_bfloat16* ws = smb + 64 * SA;       // [128][SA]  (also V-transpose staging)
    const int tid  = threadIdx.x;
    const int row0 = blockIdx.x * 64;
    const int warp = tid >> 5, lane = tid & 31;

    // --- LayerNorm -> bf16 smem ---
    for (int r = warp; r < 64; r += 8) {
        const float4 x = ((const float4*)(Z_raw + (size_t)(row0 + r) * D_DIM))[lane];
        float s  = x.x + x.y + x.z + x.w;
        float ss = x.x * x.x + x.y * x.y + x.z * x.z + x.w * x.w;
        #pragma unroll
        for (int o = 16; o > 0; o >>= 1) {
            s  += __shfl_xor_sync(0xffffffffu, s, o);
            ss += __shfl_xor_sync(0xffffffffu, ss, o);
        }
        const float mu  = s * (1.0f / 128.0f);
        const float inv = rsqrtf(ss * (1.0f / 128.0f) - mu * mu + 1e-5f);
        const int c = lane * 4;
        float v0 = (x.x - mu) * inv * __ldg(ln_w + c + 0) + __ldg(ln_b + c + 0);
        float v1 = (x.y - mu) * inv * __ldg(ln_w + c + 1) + __ldg(ln_b + c + 1);
        float v2 = (x.z - mu) * inv * __ldg(ln_w + c + 2) + __ldg(ln_b + c + 2);
        float v3 = (x.w - mu) * inv * __ldg(ln_w + c + 3) + __ldg(ln_b + c + 3);
        __nv_bfloat162* zr = (__nv_bfloat162*)(zn + r * SA + c);
        zr[0] = __float22bfloat162_rn(make_float2(v0, v1));
        zr[1] = __float22bfloat162_rn(make_float2(v2, v3));
    }
    __syncthreads();

    // --- triangle bias (bf16 out, x log2e; 2-way accumulation) ---
    {
        const int r = tid >> 2, h = tid & 3;
        float acc0 = 0.0f, acc1 = 0.0f;
        #pragma unroll 8
        for (int kk = 0; kk < D_DIM; kk += 2) {
            acc0 = fmaf(__bfloat162float(zn[r * SA + kk]),     __ldg(w_b + kk * N_HEADS + h),       acc0);
            acc1 = fmaf(__bfloat162float(zn[r * SA + kk + 1]), __ldg(w_b + (kk + 1) * N_HEADS + h), acc1);
        }
        g_trib[h * ROWS + row0 + r] = __float2bfloat16((acc0 + acc1) * LOG2E);
    }

    // --- A fragments (reused across all 4 weight matrices) ---
    const int warp_m = warp & 3, warp_n = warp >> 2;
    const int r0 = warp_m * 16 + (lane >> 2);   // local row 0..63
    const int r1 = r0 + 8;
    unsigned afr[8][4];
    #pragma unroll
    for (int kt = 0; kt < 8; kt++) {
        const __nv_bfloat16* a0 = zn + r0 * SA + kt * 16 + (lane & 3) * 2;
        const __nv_bfloat16* a1 = zn + r1 * SA + kt * 16 + (lane & 3) * 2;
        afr[kt][0] = *(const unsigned*)a0;
        afr[kt][1] = *(const unsigned*)a1;
        afr[kt][2] = *(const unsigned*)(a0 + 8);
        afr[kt][3] = *(const unsigned*)(a1 + 8);
    }

    const int iblk = row0 >> 8, jbase = row0 & 255;

    for (int m = 0; m < 4; m++) {
        __syncthreads();
        const __nv_bfloat16* Wsrc = g_wT[m];
        for (int idx = tid; idx < 2048; idx += 256) {
            const int n = idx >> 4, seg = idx & 15;
            *(uint4*)(ws + n * SA + seg * 8) = *(const uint4*)(Wsrc + n * 128 + seg * 8);
        }
        __syncthreads();

        float acc[8][4];
        #pragma unroll
        for (int nt = 0; nt < 8; nt++)
            #pragma unroll
            for (int j = 0; j < 4; j++) acc[nt][j] = 0.0f;

        #pragma unroll
        for (int kt = 0; kt < 8; kt++) {
            #pragma unroll
            for (int nt = 0; nt < 8; nt++) {
                const __nv_bfloat16* bp =
                    ws + (warp_n * 64 + nt * 8 + (lane >> 2)) * SA + kt * 16 + (lane & 3) * 2;
                unsigned b[2] = { *(const unsigned*)bp, *(const unsigned*)(bp + 8) };
                mma_bf16(acc[nt], afr[kt], b);
            }
        }

        if (m == 2) {
            // stage V transposed through smem (reuse ws)
            __syncthreads();
            #pragma unroll
            for (int nt = 0; nt < 8; nt++) {
                const int col = warp_n * 64 + nt * 8 + (lane & 3) * 2;
                ws[col * VST + r0]       = __float2bfloat16(acc[nt][0]);
                ws[(col + 1) * VST + r0] = __float2bfloat16(acc[nt][1]);
                ws[col * VST + r1]       = __float2bfloat16(acc[nt][2]);
                ws[(col + 1) * VST + r1] = __float2bfloat16(acc[nt][3]);
            }
            __syncthreads();
            for (int idx = tid; idx < 1024; idx += 256) {
                const int col = idx >> 3, seg = idx & 7;
                *(uint4*)(g_vT + (((size_t)iblk * 4 + (col >> 5)) * 32 + (col & 31)) * 256
                          + jbase + seg * 8) =
                    *(const uint4*)(ws + col * VST + seg * 8);
            }
        } else {
            const int gr0 = row0 + r0, gr1 = row0 + r1;
            #pragma unroll
            for (int nt = 0; nt < 8; nt++) {
                const int col = warp_n * 64 + nt * 8 + (lane & 3) * 2;
                const int h = col >> 5, c = col & 31;
                const int j0 = gr0 & 255, j1 = gr1 & 255;
                if (m < 2) {
                    __nv_bfloat16* dst = (m == 0) ? g_qb : g_kb;
                    *(__nv_bfloat162*)(dst + ((iblk * 4 + h) * 256 + j0) * 32 + c) =
                        __float22bfloat162_rn(make_float2(acc[nt][0], acc[nt][1]));
                    *(__nv_bfloat162*)(dst + ((iblk * 4 + h) * 256 + j1) * 32 + c) =
                        __float22bfloat162_rn(make_float2(acc[nt][2], acc[nt][3]));
                } else {
                    const float2 bgv = __ldg((const float2*)(bg + col));
                    const float g00 = 1.0f / (1.0f + __expf(-(acc[nt][0] + bgv.x)));
                    const float g01 = 1.0f / (1.0f + __expf(-(acc[nt][1] + bgv.y)));
                    const float g10 = 1.0f / (1.0f + __expf(-(acc[nt][2] + bgv.x)));
                    const float g11 = 1.0f / (1.0f + __expf(-(acc[nt][3] + bgv.y)));
                    *(__nv_bfloat162*)(g_gb + ((iblk * 4 + h) * 256 + j0) * 32 + c) =
                        __float22bfloat162_rn(make_float2(g00, g01));
                    *(__nv_bfloat162*)(g_gb + ((iblk * 4 + h) * 256 + j1) * 32 + c) =
                        __float22bfloat162_rn(make_float2(g10, g11));
                }
            }
        }
    }
}

// ---------------- kernel 2: attention per (i,h) ----------------
// R14 config (128-key tiles, occ 4) + gate prefetch at chunk top.
#define SK 40     // Ks bf16 row stride
#define SV 264    // VsT bf16 row stride
__global__ __launch_bounds__(128, 4) void k_attn(const float* __restrict__ Z_mask)
{
    extern __shared__ __nv_bfloat16 smb[];
    __nv_bfloat16* Ks  = smb;                    // [256][SK]
    __nv_bfloat16* VsT = Ks + 256 * SK;          // [32][SV]
    float* ms = (float*)(VsT + 32 * SV);         // [256]
    const int i = blockIdx.x, h = blockIdx.y;
    const int tid = threadIdx.x;
    const int warp = tid >> 5, lane = tid & 31;

    const size_t base = (size_t)(i * N_HEADS + h) * N_POS * C_DIM;
    for (int idx = tid; idx < 1024; idx += 128) {
        const int j = idx >> 2, seg = idx & 3;
        *(uint4*)(Ks + j * SK + seg * 8) = *(const uint4*)(g_kb + base + j * 32 + seg * 8);
    }
    for (int idx = tid; idx < 1024; idx += 128) {
        const int c = idx >> 5, seg = idx & 31;
        *(uint4*)(VsT + c * SV + seg * 8) = *(const uint4*)(g_vT + base + c * 256 + seg * 8);
    }
    for (int kk = tid; kk < 256; kk += 128)
        ms[kk] = (1e9f * LOG2E) * (__ldg(Z_mask + i * N_POS + kk) - 1.0f);
    __syncthreads();

    const __nv_bfloat16* tribh = g_trib + (size_t)h * ROWS;
    const int qt = (lane & 3) * 2;

    for (int chunk = 0; chunk < 4; chunk++) {
        const int r0 = chunk * 64 + warp * 16 + (lane >> 2);
        const int r1 = r0 + 8;

        unsigned qa[2][4];
        {
            const __nv_bfloat16* q0 = g_qb + base + (size_t)r0 * 32 + qt;
            const __nv_bfloat16* q1 = g_qb + base + (size_t)r1 * 32 + qt;
            #pragma unroll
            for (int kt = 0; kt < 2; kt++) {
                qa[kt][0] = *(const unsigned*)(q0 + kt * 16);
                qa[kt][1] = *(const unsigned*)(q1 + kt * 16);
                qa[kt][2] = *(const unsigned*)(q0 + kt * 16 + 8);
                qa[kt][3] = *(const unsigned*)(q1 + kt * 16 + 8);
            }
        }

        // prefetch gate values (consumed in the epilogue ~3000 cycles later)
        unsigned gpre0[4], gpre1[4];
        #pragma unroll
        for (int vt = 0; vt < 4; vt++) {
            gpre0[vt] = *(const unsigned*)(g_gb + base + (size_t)r0 * 32 + vt * 8 + qt);
            gpre1[vt] = *(const unsigned*)(g_gb + base + (size_t)r1 * 32 + vt * 8 + qt);
        }

        float oacc[4][4];
        #pragma unroll
        for (int vt = 0; vt < 4; vt++)
            #pragma unroll
            for (int j = 0; j < 4; j++) oacc[vt][j] = 0.0f;
        float s0 = 0.0f, s1 = 0.0f;

        const __nv_bfloat16* t0p = tribh + (size_t)r0 * 256;
        const __nv_bfloat16* t1p = tribh + (size_t)r1 * 256;

        #pragma unroll
        for (int kb = 0; kb < 2; kb++) {
            float sacc[16][4];
            #pragma unroll
            for (int nt = 0; nt < 16; nt++) {
                const int col = kb * 128 + nt * 8 + qt;
                const float2 tb0 = __bfloat1622float2(*(const __nv_bfloat162*)(t0p + col));
                const float2 tb1 = __bfloat1622float2(*(const __nv_bfloat162*)(t1p + col));
                const float2 mv  = *(const float2*)(ms + col);
                sacc[nt][0] = tb0.x + mv.x; sacc[nt][1] = tb0.y + mv.y;
                sacc[nt][2] = tb1.x + mv.x; sacc[nt][3] = tb1.y + mv.y;
            }
            #pragma unroll
            for (int nt = 0; nt < 16; nt++) {
                const __nv_bfloat16* kp =
                    Ks + (kb * 128 + nt * 8 + (lane >> 2)) * SK + qt;
                unsigned b0[2] = { *(const unsigned*)kp,        *(const unsigned*)(kp + 8) };
                mma_bf16(sacc[nt], qa[0], b0);
                unsigned b1[2] = { *(const unsigned*)(kp + 16), *(const unsigned*)(kp + 24) };
                mma_bf16(sacc[nt], qa[1], b1);
            }
            #pragma unroll
            for (int nt = 0; nt < 16; nt++) {
                sacc[nt][0] = ex2(sacc[nt][0]); s0 += sacc[nt][0];
                sacc[nt][1] = ex2(sacc[nt][1]); s0 += sacc[nt][1];
                sacc[nt][2] = ex2(sacc[nt][2]); s1 += sacc[nt][2];
                sacc[nt][3] = ex2(sacc[nt][3]); s1 += sacc[nt][3];
            }
            #pragma unroll
            for (int kt = 0; kt < 8; kt++) {
                unsigned pa[4];
                pa[0] = pack_bf16(sacc[2 * kt][0],     sacc[2 * kt][1]);
                pa[1] = pack_bf16(sacc[2 * kt][2],     sacc[2 * kt][3]);
                pa[2] = pack_bf16(sacc[2 * kt + 1][0], sacc[2 * kt + 1][1]);
                pa[3] = pack_bf16(sacc[2 * kt + 1][2], sacc[2 * kt + 1][3]);
                #pragma unroll
                for (int vt = 0; vt < 4; vt++) {
                    const __nv_bfloat16* vp =
                        VsT + (vt * 8 + (lane >> 2)) * SV + kb * 128 + kt * 16 + qt;
                    unsigned b[2] = { *(const unsigned*)vp, *(const unsigned*)(vp + 8) };
                    mma_bf16(oacc[vt], pa, b);
                }
            }
        }

        s0 += __shfl_xor_sync(0xffffffffu, s0, 1);
        s0 += __shfl_xor_sync(0xffffffffu, s0, 2);
        s1 += __shfl_xor_sync(0xffffffffu, s1, 1);
        s1 += __shfl_xor_sync(0xffffffffu, s1, 2);
        const float inv0 = frcp(s0), inv1 = frcp(s1);

        const size_t grow0 = (size_t)i * 256 + r0;
        const size_t grow1 = (size_t)i * 256 + r1;
        #pragma unroll
        for (int vt = 0; vt < 4; vt++) {
            const int colc = vt * 8 + qt;
            const float2 gv0 = __bfloat1622float2(*(const __nv_bfloat162*)&gpre0[vt]);
            const float2 gv1 = __bfloat1622float2(*(const __nv_bfloat162*)&gpre1[vt]);
            *(__nv_bfloat162*)(g_ogb + grow0 * D_DIM + h * 32 + colc) =
                __float22bfloat162_rn(make_float2(oacc[vt][0] * inv0 * gv0.x,
                                                  oacc[vt][1] * inv0 * gv0.y));
            *(__nv_bfloat162*)(g_ogb + grow1 * D_DIM + h * 32 + colc) =
                __float22bfloat162_rn(make_float2(oacc[vt][2] * inv1 * gv1.x,
                                                  oacc[vt][3] * inv1 * gv1.y));
        }
    }
}

// ---------------- kernel 3: output projection + bias + residual ----------------
// R6 structure + ldmatrix B-fragments (measured win in R12: 29.6us).
__global__ __launch_bounds__(256) void k_out(
    const float* __restrict__ Z_raw,
    const float* __restrict__ out_bias, float* __restrict__ out)
{
    extern __shared__ __nv_bfloat16 smb[];
    __nv_bfloat16* os = smb;                 // [64][SA]
    __nv_bfloat16* ws = smb + 64 * SA;       // [128][SA]
    const int tid  = threadIdx.x;
    const int warp = tid >> 5, lane = tid & 31;
    const int warp_m = warp & 3, warp_n = warp >> 2;
    const int lr0 = warp_m * 16 + (lane >> 2);
    const int lr1 = lr0 + 8;

    for (int idx = tid; idx < 2048; idx += 256) {
        const int n = idx >> 4, seg = idx & 15;
        *(uint4*)(ws + n * SA + seg * 8) = *(const uint4*)(g_woT + n * 128 + seg * 8);
    }

    for (int t = 0; t < 2; t++) {
        const int row0 = blockIdx.x * 128 + t * 64;
        __syncthreads();
        for (int idx = tid; idx < 1024; idx += 256) {
            const int r = idx >> 4, seg = idx & 15;
            *(uint4*)(os + r * SA + seg * 8) =
                *(const uint4*)(g_ogb + (size_t)(row0 + r) * D_DIM + seg * 8);
        }
        __syncthreads();

        unsigned afr[8][4];
        #pragma unroll
        for (int kt = 0; kt < 8; kt++) {
            const __nv_bfloat16* a0 = os + lr0 * SA + kt * 16 + (lane & 3) * 2;
            const __nv_bfloat16* a1 = os + lr1 * SA + kt * 16 + (lane & 3) * 2;
            afr[kt][0] = *(const unsigned*)a0;
            afr[kt][1] = *(const unsigned*)a1;
            afr[kt][2] = *(const unsigned*)(a0 + 8);
            afr[kt][3] = *(const unsigned*)(a1 + 8);
        }

        float acc[8][4];
        #pragma unroll
        for (int nt = 0; nt < 8; nt++)
            #pragma unroll
            for (int j = 0; j < 4; j++) acc[nt][j] = 0.0f;

        #pragma unroll
        for (int kt = 0; kt < 8; kt++) {
            #pragma unroll
            for (int np = 0; np < 4; np++) {
                unsigned bm[4];
                const __nv_bfloat16* bp =
                    ws + (warp_n * 64 + np * 16 + (lane >> 4) * 8 + (lane & 7)) * SA
                       + kt * 16 + ((lane >> 3) & 1) * 8;
                ldsm_x4(bm, bp);
                mma_bf16(acc[np * 2],     afr[kt], bm);
                mma_bf16(acc[np * 2 + 1], afr[kt], bm + 2);
            }
        }

        const size_t gr0 = row0 + lr0, gr1 = row0 + lr1;
        #pragma unroll
        for (int nt = 0; nt < 8; nt++) {
            const int col = warp_n * 64 + nt * 8 + (lane & 3) * 2;
            const float2 ob = *(const float2*)(out_bias + col);
            const float2 z0 = *(const float2*)(Z_raw + gr0 * D_DIM + col);
            const float2 z1 = *(const float2*)(Z_raw + gr1 * D_DIM + col);
            *(float2*)(out + gr0 * D_DIM + col) =
                make_float2(acc[nt][0] + ob.x + z0.x, acc[nt][1] + ob.y + z0.y);
            *(float2*)(out + gr1 * D_DIM + col) =
                make_float2(acc[nt][2] + ob.x + z1.x, acc[nt][3] + ob.y + z1.y);
        }
    }
}

// ---------------------------------------------------------------------------
extern "C" void kernel_launch(void* const* d_in, const int* in_sizes, int n_in,
                              void* d_out, int out_size)
{
    (void)in_sizes; (void)n_in; (void)out_size;
    const float* Z_raw    = (const float*)d_in[0];
    const float* Z_mask   = (const float*)d_in[1];
    const float* ln_w     = (const float*)d_in[2];
    const float* ln_b     = (const float*)d_in[3];
    const float* w_b      = (const float*)d_in[4];
    const float* wq       = (const float*)d_in[5];
    const float* wk       = (const float*)d_in[6];
    const float* wv       = (const float*)d_in[7];
    const float* wg       = (const float*)d_in[8];
    const float* bg       = (const float*)d_in[9];
    const float* wo       = (const float*)d_in[10];
    const float* out_bias = (const float*)d_in[11];
    float* out = (float*)d_out;

    const int smem_gemm = (64 * SA + 128 * SA) * 2;                    // 52224
    const int smem_attn = (256 * SK + 32 * SV) * 2 + 256 * 4;          // 38400

    cudaFuncSetAttribute(k_proj, cudaFuncAttributeMaxDynamicSharedMemorySize, smem_gemm);
    cudaFuncSetAttribute(k_attn, cudaFuncAttributeMaxDynamicSharedMemorySize, smem_attn);
    cudaFuncSetAttribute(k_out,  cudaFuncAttributeMaxDynamicSharedMemorySize, smem_gemm);

    k_setup<<<160, 256>>>(wq, wk, wv, wg, wo);
    k_proj<<<ROWS / 64, 256, smem_gemm>>>(Z_raw, ln_w, ln_b, w_b, bg);
    k_attn<<<dim3(N_POS, N_HEADS), 128, smem_attn>>>(Z_mask);
    k_out<<<ROWS / 128, 256, smem_gemm>>>(Z_raw, out_bias, out);
}

// round 17
// speedup vs baseline: 1.0966x; 1.0124x over previous
#include <cuda_runtime.h>
#include <cuda_bf16.h>
#include <math.h>

#define N_POS 256
#define D_DIM 128
#define N_HEADS 4
#define C_DIM 32
#define ROWS (N_POS * N_POS)   // 65536

#define LOG2E 1.4426950408889634f

// ---------------- scratch (static device arrays) ----------------
__device__ __nv_bfloat16 g_qb[N_POS * N_HEADS * N_POS * C_DIM];   // [i][h][j][c]
__device__ __nv_bfloat16 g_kb[N_POS * N_HEADS * N_POS * C_DIM];   // [i][h][j][c]
__device__ __nv_bfloat16 g_vT[N_POS * N_HEADS * C_DIM * N_POS];   // [i][h][c][j]
__device__ __nv_bfloat16 g_gb[N_POS * N_HEADS * N_POS * C_DIM];   // sigmoid gate [i][h][j][c]
__device__ __nv_bfloat16 g_ogb[ROWS * D_DIM];                     // gated attn out (bf16)
__device__ __nv_bfloat16 g_trib[N_HEADS * ROWS];                  // [h][q*256+k] bf16 (x log2e)
__device__ __nv_bfloat16 g_wT[4][D_DIM * D_DIM];                  // q,k,v,g as [n][k] bf16
__device__ __nv_bfloat16 g_woT[D_DIM * D_DIM];                    // [d][hc] bf16

// ---------------- helpers ----------------
__device__ __forceinline__ void mma_bf16(float* c, const unsigned* a, const unsigned* b) {
    asm volatile(
        "mma.sync.aligned.m16n8k16.row.col.f32.bf16.bf16.f32 "
        "{%0,%1,%2,%3}, {%4,%5,%6,%7}, {%8,%9}, {%0,%1,%2,%3};\n"
        : "+f"(c[0]), "+f"(c[1]), "+f"(c[2]), "+f"(c[3])
        : "r"(a[0]), "r"(a[1]), "r"(a[2]), "r"(a[3]), "r"(b[0]), "r"(b[1]));
}

__device__ __forceinline__ void ldsm_x4(unsigned* d, const __nv_bfloat16* p) {
    unsigned addr = (unsigned)__cvta_generic_to_shared(p);
    asm volatile("ldmatrix.sync.aligned.m8n8.x4.shared.b16 {%0,%1,%2,%3}, [%4];"
        : "=r"(d[0]), "=r"(d[1]), "=r"(d[2]), "=r"(d[3]) : "r"(addr));
}

__device__ __forceinline__ unsigned pack_bf16(float lo, float hi) {
    __nv_bfloat162 t = __float22bfloat162_rn(make_float2(lo, hi));
    return *(unsigned*)&t;
}

__device__ __forceinline__ float ex2(float x) {
    float y;
    asm("ex2.approx.ftz.f32 %0, %1;" : "=f"(y) : "f"(x));
    return y;
}

__device__ __forceinline__ float frcp(float x) {
    float y;
    asm("rcp.approx.ftz.f32 %0, %1;" : "=f"(y) : "f"(x));
    return y;
}

// ---------------- kernel 0: weight transpose to bf16 ----------------
__global__ __launch_bounds__(256) void k_setup(
    const float* __restrict__ wq, const float* __restrict__ wk,
    const float* __restrict__ wv, const float* __restrict__ wg,
    const float* __restrict__ wo)
{
    for (int idx = blockIdx.x * 256 + threadIdx.x; idx < 5 * 16384; idx += gridDim.x * 256) {
        const int m = idx >> 14, r = idx & 16383;
        const int k = r >> 7, n = r & 127;
        const float* src = (m == 0) ? wq : (m == 1) ? wk : (m == 2) ? wv : (m == 3) ? wg : wo;
        float v = __ldg(src + r);
        if (m == 0) v *= 0.17677669529663687f * LOG2E;   // c^-0.5 and log2e folded into wq
        __nv_bfloat16 bv = __float2bfloat16(v);
        if (m < 4) g_wT[m][n * 128 + k] = bv;
        else       g_woT[n * 128 + k] = bv;
    }
}

// ---------------- kernel 1: LN + 4 projections + triangle bias ----------------
#define SA 136   // bf16 row stride (GEMM smem)
#define VST 72   // V staging stride (bf16)
__global__ __launch_bounds__(256) void k_proj(
    const float* __restrict__ Z_raw,
    const float* __restrict__ ln_w, const float* __restrict__ ln_b,
    const float* __restrict__ w_b, const float* __restrict__ bg)
{
    extern __shared__ __nv_bfloat16 smb[];
    __nv_bfloat16* zn = smb;                 // [64][SA]
    __nv_bfloat16* ws = smb + 64 * SA;       // [128][SA]  (also V-transpose staging)
    const int tid  = threadIdx.x;
    const int row0 = blockIdx.x * 64;
    const int warp = tid >> 5, lane = tid & 31;

    // --- LayerNorm -> bf16 smem ---
    for (int r = warp; r < 64; r += 8) {
        const float4 x = ((const float4*)(Z_raw + (size_t)(row0 + r) * D_DIM))[lane];
        float s  = x.x + x.y + x.z + x.w;
        float ss = x.x * x.x + x.y * x.y + x.z * x.z + x.w * x.w;
        #pragma unroll
        for (int o = 16; o > 0; o >>= 1) {
            s  += __shfl_xor_sync(0xffffffffu, s, o);
            ss += __shfl_xor_sync(0xffffffffu, ss, o);
        }
        const float mu  = s * (1.0f / 128.0f);
        const float inv = rsqrtf(ss * (1.0f / 128.0f) - mu * mu + 1e-5f);
        const int c = lane * 4;
        float v0 = (x.x - mu) * inv * __ldg(ln_w + c + 0) + __ldg(ln_b + c + 0);
        float v1 = (x.y - mu) * inv * __ldg(ln_w + c + 1) + __ldg(ln_b + c + 1);
        float v2 = (x.z - mu) * inv * __ldg(ln_w + c + 2) + __ldg(ln_b + c + 2);
        float v3 = (x.w - mu) * inv * __ldg(ln_w + c + 3) + __ldg(ln_b + c + 3);
        __nv_bfloat162* zr = (__nv_bfloat162*)(zn + r * SA + c);
        zr[0] = __float22bfloat162_rn(make_float2(v0, v1));
        zr[1] = __float22bfloat162_rn(make_float2(v2, v3));
    }
    __syncthreads();

    // --- triangle bias (bf16 out, x log2e; 2-way accumulation) ---
    {
        const int r = tid >> 2, h = tid & 3;
        float acc0 = 0.0f, acc1 = 0.0f;
        #pragma unroll 8
        for (int kk = 0; kk < D_DIM; kk += 2) {
            acc0 = fmaf(__bfloat162float(zn[r * SA + kk]),     __ldg(w_b + kk * N_HEADS + h),       acc0);
            acc1 = fmaf(__bfloat162float(zn[r * SA + kk + 1]), __ldg(w_b + (kk + 1) * N_HEADS + h), acc1);
        }
        g_trib[h * ROWS + row0 + r] = __float2bfloat16((acc0 + acc1) * LOG2E);
    }

    // --- A fragments (reused across all 4 weight matrices) ---
    const int warp_m = warp & 3, warp_n = warp >> 2;
    const int r0 = warp_m * 16 + (lane >> 2);   // local row 0..63
    const int r1 = r0 + 8;
    unsigned afr[8][4];
    #pragma unroll
    for (int kt = 0; kt < 8; kt++) {
        const __nv_bfloat16* a0 = zn + r0 * SA + kt * 16 + (lane & 3) * 2;
        const __nv_bfloat16* a1 = zn + r1 * SA + kt * 16 + (lane & 3) * 2;
        afr[kt][0] = *(const unsigned*)a0;
        afr[kt][1] = *(const unsigned*)a1;
        afr[kt][2] = *(const unsigned*)(a0 + 8);
        afr[kt][3] = *(const unsigned*)(a1 + 8);
    }

    const int iblk = row0 >> 8, jbase = row0 & 255;

    for (int m = 0; m < 4; m++) {
        __syncthreads();
        const __nv_bfloat16* Wsrc = g_wT[m];
        for (int idx = tid; idx < 2048; idx += 256) {
            const int n = idx >> 4, seg = idx & 15;
            *(uint4*)(ws + n * SA + seg * 8) = *(const uint4*)(Wsrc + n * 128 + seg * 8);
        }
        __syncthreads();

        float acc[8][4];
        #pragma unroll
        for (int nt = 0; nt < 8; nt++)
            #pragma unroll
            for (int j = 0; j < 4; j++) acc[nt][j] = 0.0f;

        #pragma unroll
        for (int kt = 0; kt < 8; kt++) {
            #pragma unroll
            for (int nt = 0; nt < 8; nt++) {
                const __nv_bfloat16* bp =
                    ws + (warp_n * 64 + nt * 8 + (lane >> 2)) * SA + kt * 16 + (lane & 3) * 2;
                unsigned b[2] = { *(const unsigned*)bp, *(const unsigned*)(bp + 8) };
                mma_bf16(acc[nt], afr[kt], b);
            }
        }

        if (m == 2) {
            // stage V transposed through smem (reuse ws)
            __syncthreads();
            #pragma unroll
            for (int nt = 0; nt < 8; nt++) {
                const int col = warp_n * 64 + nt * 8 + (lane & 3) * 2;
                ws[col * VST + r0]       = __float2bfloat16(acc[nt][0]);
                ws[(col + 1) * VST + r0] = __float2bfloat16(acc[nt][1]);
                ws[col * VST + r1]       = __float2bfloat16(acc[nt][2]);
                ws[(col + 1) * VST + r1] = __float2bfloat16(acc[nt][3]);
            }
            __syncthreads();
            for (int idx = tid; idx < 1024; idx += 256) {
                const int col = idx >> 3, seg = idx & 7;
                *(uint4*)(g_vT + (((size_t)iblk * 4 + (col >> 5)) * 32 + (col & 31)) * 256
                          + jbase + seg * 8) =
                    *(const uint4*)(ws + col * VST + seg * 8);
            }
        } else {
            const int gr0 = row0 + r0, gr1 = row0 + r1;
            #pragma unroll
            for (int nt = 0; nt < 8; nt++) {
                const int col = warp_n * 64 + nt * 8 + (lane & 3) * 2;
                const int h = col >> 5, c = col & 31;
                const int j0 = gr0 & 255, j1 = gr1 & 255;
                if (m < 2) {
                    __nv_bfloat16* dst = (m == 0) ? g_qb : g_kb;
                    *(__nv_bfloat162*)(dst + ((iblk * 4 + h) * 256 + j0) * 32 + c) =
                        __float22bfloat162_rn(make_float2(acc[nt][0], acc[nt][1]));
                    *(__nv_bfloat162*)(dst + ((iblk * 4 + h) * 256 + j1) * 32 + c) =
                        __float22bfloat162_rn(make_float2(acc[nt][2], acc[nt][3]));
                } else {
                    const float2 bgv = __ldg((const float2*)(bg + col));
                    const float g00 = 1.0f / (1.0f + __expf(-(acc[nt][0] + bgv.x)));
                    const float g01 = 1.0f / (1.0f + __expf(-(acc[nt][1] + bgv.y)));
                    const float g10 = 1.0f / (1.0f + __expf(-(acc[nt][2] + bgv.x)));
                    const float g11 = 1.0f / (1.0f + __expf(-(acc[nt][3] + bgv.y)));
                    *(__nv_bfloat162*)(g_gb + ((iblk * 4 + h) * 256 + j0) * 32 + c) =
                        __float22bfloat162_rn(make_float2(g00, g01));
                    *(__nv_bfloat162*)(g_gb + ((iblk * 4 + h) * 256 + j1) * 32 + c) =
                        __float22bfloat162_rn(make_float2(g10, g11));
                }
            }
        }
    }
}

// ---------------- kernel 2: attention per (i,h) ----------------
// R16 config + trib/mask folded into the ex2 phase (MMAs start immediately,
// sacc zero-init; bias loads no longer gate the tensor pipe).
#define SK 40     // Ks bf16 row stride
#define SV 264    // VsT bf16 row stride
__global__ __launch_bounds__(128, 4) void k_attn(const float* __restrict__ Z_mask)
{
    extern __shared__ __nv_bfloat16 smb[];
    __nv_bfloat16* Ks  = smb;                    // [256][SK]
    __nv_bfloat16* VsT = Ks + 256 * SK;          // [32][SV]
    float* ms = (float*)(VsT + 32 * SV);         // [256]
    const int i = blockIdx.x, h = blockIdx.y;
    const int tid = threadIdx.x;
    const int warp = tid >> 5, lane = tid & 31;

    const size_t base = (size_t)(i * N_HEADS + h) * N_POS * C_DIM;
    for (int idx = tid; idx < 1024; idx += 128) {
        const int j = idx >> 2, seg = idx & 3;
        *(uint4*)(Ks + j * SK + seg * 8) = *(const uint4*)(g_kb + base + j * 32 + seg * 8);
    }
    for (int idx = tid; idx < 1024; idx += 128) {
        const int c = idx >> 5, seg = idx & 31;
        *(uint4*)(VsT + c * SV + seg * 8) = *(const uint4*)(g_vT + base + c * 256 + seg * 8);
    }
    for (int kk = tid; kk < 256; kk += 128)
        ms[kk] = (1e9f * LOG2E) * (__ldg(Z_mask + i * N_POS + kk) - 1.0f);
    __syncthreads();

    const __nv_bfloat16* tribh = g_trib + (size_t)h * ROWS;
    const int qt = (lane & 3) * 2;

    for (int chunk = 0; chunk < 4; chunk++) {
        const int r0 = chunk * 64 + warp * 16 + (lane >> 2);
        const int r1 = r0 + 8;

        unsigned qa[2][4];
        {
            const __nv_bfloat16* q0 = g_qb + base + (size_t)r0 * 32 + qt;
            const __nv_bfloat16* q1 = g_qb + base + (size_t)r1 * 32 + qt;
            #pragma unroll
            for (int kt = 0; kt < 2; kt++) {
                qa[kt][0] = *(const unsigned*)(q0 + kt * 16);
                qa[kt][1] = *(const unsigned*)(q1 + kt * 16);
                qa[kt][2] = *(const unsigned*)(q0 + kt * 16 + 8);
                qa[kt][3] = *(const unsigned*)(q1 + kt * 16 + 8);
            }
        }

        // prefetch gate values (consumed in the epilogue ~3000 cycles later)
        unsigned gpre0[4], gpre1[4];
        #pragma unroll
        for (int vt = 0; vt < 4; vt++) {
            gpre0[vt] = *(const unsigned*)(g_gb + base + (size_t)r0 * 32 + vt * 8 + qt);
            gpre1[vt] = *(const unsigned*)(g_gb + base + (size_t)r1 * 32 + vt * 8 + qt);
        }

        float oacc[4][4];
        #pragma unroll
        for (int vt = 0; vt < 4; vt++)
            #pragma unroll
            for (int j = 0; j < 4; j++) oacc[vt][j] = 0.0f;
        float s0 = 0.0f, s1 = 0.0f;

        const __nv_bfloat16* t0p = tribh + (size_t)r0 * 256;
        const __nv_bfloat16* t1p = tribh + (size_t)r1 * 256;

        #pragma unroll
        for (int kb = 0; kb < 2; kb++) {
            float sacc[16][4];
            #pragma unroll
            for (int nt = 0; nt < 16; nt++)
                #pragma unroll
                for (int j = 0; j < 4; j++) sacc[nt][j] = 0.0f;

            // S = Q K^T (starts immediately; no bias-load dependency)
            #pragma unroll
            for (int nt = 0; nt < 16; nt++) {
                const __nv_bfloat16* kp =
                    Ks + (kb * 128 + nt * 8 + (lane >> 2)) * SK + qt;
                unsigned b0[2] = { *(const unsigned*)kp,        *(const unsigned*)(kp + 8) };
                mma_bf16(sacc[nt], qa[0], b0);
                unsigned b1[2] = { *(const unsigned*)(kp + 16), *(const unsigned*)(kp + 24) };
                mma_bf16(sacc[nt], qa[1], b1);
            }
            // P = exp2(S + trib + mask)
            #pragma unroll
            for (int nt = 0; nt < 16; nt++) {
                const int col = kb * 128 + nt * 8 + qt;
                const float2 tb0 = __bfloat1622float2(*(const __nv_bfloat162*)(t0p + col));
                const float2 tb1 = __bfloat1622float2(*(const __nv_bfloat162*)(t1p + col));
                const float2 mv  = *(const float2*)(ms + col);
                sacc[nt][0] = ex2(sacc[nt][0] + tb0.x + mv.x); s0 += sacc[nt][0];
                sacc[nt][1] = ex2(sacc[nt][1] + tb0.y + mv.y); s0 += sacc[nt][1];
                sacc[nt][2] = ex2(sacc[nt][2] + tb1.x + mv.x); s1 += sacc[nt][2];
                sacc[nt][3] = ex2(sacc[nt][3] + tb1.y + mv.y); s1 += sacc[nt][3];
            }
            // O += P V
            #pragma unroll
            for (int kt = 0; kt < 8; kt++) {
                unsigned pa[4];
                pa[0] = pack_bf16(sacc[2 * kt][0],     sacc[2 * kt][1]);
                pa[1] = pack_bf16(sacc[2 * kt][2],     sacc[2 * kt][3]);
                pa[2] = pack_bf16(sacc[2 * kt + 1][0], sacc[2 * kt + 1][1]);
                pa[3] = pack_bf16(sacc[2 * kt + 1][2], sacc[2 * kt + 1][3]);
                #pragma unroll
                for (int vt = 0; vt < 4; vt++) {
                    const __nv_bfloat16* vp =
                        VsT + (vt * 8 + (lane >> 2)) * SV + kb * 128 + kt * 16 + qt;
                    unsigned b[2] = { *(const unsigned*)vp, *(const unsigned*)(vp + 8) };
                    mma_bf16(oacc[vt], pa, b);
                }
            }
        }

        s0 += __shfl_xor_sync(0xffffffffu, s0, 1);
        s0 += __shfl_xor_sync(0xffffffffu, s0, 2);
        s1 += __shfl_xor_sync(0xffffffffu, s1, 1);
        s1 += __shfl_xor_sync(0xffffffffu, s1, 2);
        const float inv0 = frcp(s0), inv1 = frcp(s1);

        const size_t grow0 = (size_t)i * 256 + r0;
        const size_t grow1 = (size_t)i * 256 + r1;
        #pragma unroll
        for (int vt = 0; vt < 4; vt++) {
            const int colc = vt * 8 + qt;
            const float2 gv0 = __bfloat1622float2(*(const __nv_bfloat162*)&gpre0[vt]);
            const float2 gv1 = __bfloat1622float2(*(const __nv_bfloat162*)&gpre1[vt]);
            *(__nv_bfloat162*)(g_ogb + grow0 * D_DIM + h * 32 + colc) =
                __float22bfloat162_rn(make_float2(oacc[vt][0] * inv0 * gv0.x,
                                                  oacc[vt][1] * inv0 * gv0.y));
            *(__nv_bfloat162*)(g_ogb + grow1 * D_DIM + h * 32 + colc) =
                __float22bfloat162_rn(make_float2(oacc[vt][2] * inv1 * gv1.x,
                                                  oacc[vt][3] * inv1 * gv1.y));
        }
    }
}

// ---------------- kernel 3: output projection + bias + residual ----------------
// R6 structure + ldmatrix B-fragments (measured win in R12: 29.6us).
__global__ __launch_bounds__(256) void k_out(
    const float* __restrict__ Z_raw,
    const float* __restrict__ out_bias, float* __restrict__ out)
{
    extern __shared__ __nv_bfloat16 smb[];
    __nv_bfloat16* os = smb;                 // [64][SA]
    __nv_bfloat16* ws = smb + 64 * SA;       // [128][SA]
    const int tid  = threadIdx.x;
    const int warp = tid >> 5, lane = tid & 31;
    const int warp_m = warp & 3, warp_n = warp >> 2;
    const int lr0 = warp_m * 16 + (lane >> 2);
    const int lr1 = lr0 + 8;

    for (int idx = tid; idx < 2048; idx += 256) {
        const int n = idx >> 4, seg = idx & 15;
        *(uint4*)(ws + n * SA + seg * 8) = *(const uint4*)(g_woT + n * 128 + seg * 8);
    }

    for (int t = 0; t < 2; t++) {
        const int row0 = blockIdx.x * 128 + t * 64;
        __syncthreads();
        for (int idx = tid; idx < 1024; idx += 256) {
            const int r = idx >> 4, seg = idx & 15;
            *(uint4*)(os + r * SA + seg * 8) =
                *(const uint4*)(g_ogb + (size_t)(row0 + r) * D_DIM + seg * 8);
        }
        __syncthreads();

        unsigned afr[8][4];
        #pragma unroll
        for (int kt = 0; kt < 8; kt++) {
            const __nv_bfloat16* a0 = os + lr0 * SA + kt * 16 + (lane & 3) * 2;
            const __nv_bfloat16* a1 = os + lr1 * SA + kt * 16 + (lane & 3) * 2;
            afr[kt][0] = *(const unsigned*)a0;
            afr[kt][1] = *(const unsigned*)a1;
            afr[kt][2] = *(const unsigned*)(a0 + 8);
            afr[kt][3] = *(const unsigned*)(a1 + 8);
        }

        float acc[8][4];
        #pragma unroll
        for (int nt = 0; nt < 8; nt++)
            #pragma unroll
            for (int j = 0; j < 4; j++) acc[nt][j] = 0.0f;

        #pragma unroll
        for (int kt = 0; kt < 8; kt++) {
            #pragma unroll
            for (int np = 0; np < 4; np++) {
                unsigned bm[4];
                const __nv_bfloat16* bp =
                    ws + (warp_n * 64 + np * 16 + (lane >> 4) * 8 + (lane & 7)) * SA
                       + kt * 16 + ((lane >> 3) & 1) * 8;
                ldsm_x4(bm, bp);
                mma_bf16(acc[np * 2],     afr[kt], bm);
                mma_bf16(acc[np * 2 + 1], afr[kt], bm + 2);
            }
        }

        const size_t gr0 = row0 + lr0, gr1 = row0 + lr1;
        #pragma unroll
        for (int nt = 0; nt < 8; nt++) {
            const int col = warp_n * 64 + nt * 8 + (lane & 3) * 2;
            const float2 ob = *(const float2*)(out_bias + col);
            const float2 z0 = *(const float2*)(Z_raw + gr0 * D_DIM + col);
            const float2 z1 = *(const float2*)(Z_raw + gr1 * D_DIM + col);
            *(float2*)(out + gr0 * D_DIM + col) =
                make_float2(acc[nt][0] + ob.x + z0.x, acc[nt][1] + ob.y + z0.y);
            *(float2*)(out + gr1 * D_DIM + col) =
                make_float2(acc[nt][2] + ob.x + z1.x, acc[nt][3] + ob.y + z1.y);
        }
    }
}

// ---------------------------------------------------------------------------
extern "C" void kernel_launch(void* const* d_in, const int* in_sizes, int n_in,
                              void* d_out, int out_size)
{
    (void)in_sizes; (void)n_in; (void)out_size;
    const float* Z_raw    = (const float*)d_in[0];
    const float* Z_mask   = (const float*)d_in[1];
    const float* ln_w     = (const float*)d_in[2];
    const float* ln_b     = (const float*)d_in[3];
    const float* w_b      = (const float*)d_in[4];
    const float* wq       = (const float*)d_in[5];
    const float* wk       = (const float*)d_in[6];
    const float* wv       = (const float*)d_in[7];
    const float* wg       = (const float*)d_in[8];
    const float* bg       = (const float*)d_in[9];
    const float* wo       = (const float*)d_in[10];
    const float* out_bias = (const float*)d_in[11];
    float* out = (float*)d_out;

    const int smem_gemm = (64 * SA + 128 * SA) * 2;                    // 52224
    const int smem_attn = (256 * SK + 32 * SV) * 2 + 256 * 4;          // 38400

    cudaFuncSetAttribute(k_proj, cudaFuncAttributeMaxDynamicSharedMemorySize, smem_gemm);
    cudaFuncSetAttribute(k_attn, cudaFuncAttributeMaxDynamicSharedMemorySize, smem_attn);
    cudaFuncSetAttribute(k_out,  cudaFuncAttributeMaxDynamicSharedMemorySize, smem_gemm);

    k_setup<<<160, 256>>>(wq, wk, wv, wg, wo);
    k_proj<<<ROWS / 64, 256, smem_gemm>>>(Z_raw, ln_w, ln_b, w_b, bg);
    k_attn<<<dim3(N_POS, N_HEADS), 128, smem_attn>>>(Z_mask);
    k_out<<<ROWS / 128, 256, smem_gemm>>>(Z_raw, out_bias, out);
}